// round 12
// baseline (speedup 1.0000x reference)
#include <cuda_runtime.h>
#include <cuda_fp16.h>
#include <cstdint>

#define NN 20000
#define EE 320000
#define CC 256
#define GG 50
#define JKW 768
#define KDIM 512
#define HSZ (NN * CC)
#define NB 79                     // ceil(20000/256) scan blocks
#define CSRB 148                  // CSR builder blocks (1/SM, co-resident)
#define OUTSZ (GG * JKW + GG * 2) // 38500

#define STG_BYTES 20480          // A 10240 | B 10240
#define NSTG 4
#define SMEM_TOT (NSTG * STG_BYTES) // 80 KB, quad buffered

// ---- scratch (static device globals; no runtime allocation) ----
__device__ int   g_degi[NN];
__device__ int   g_cnt[NN];
__device__ float g_dis[NN];
__device__ int   g_rowptr[NN + 1];
__device__ int   g_bsum[NB];
__device__ int   g_gcnt;
__device__ volatile int g_gphase;
__device__ int   g_ccol[EE];
__device__ float g_cw[EE];
__device__ __align__(16) __half g_hb[2 * HSZ];      // h fp16, ping-pong by layer
__device__ __align__(16) __half g_pb[HSZ];          // p fp16
__device__ __align__(16) __half g_wb[3 * CC * KDIM];// W^T fp16 [l][n][k]
__device__ int   g_gstart[GG];
__device__ int   g_gend[GG];

// ---------------- helpers ----------------
__device__ __forceinline__ uint32_t smem_u32(const void* p) {
    uint32_t a;
    asm("{ .reg .u64 t; cvta.to.shared.u64 t, %1; cvt.u32.u64 %0, t; }" : "=r"(a) : "l"(p));
    return a;
}

// L1-bypassing bulk async copy (cg = cache-global)
__device__ __forceinline__ void cpa16(uint32_t dst, const void* src, int sz) {
    asm volatile("cp.async.cg.shared.global [%0], [%1], 16, %2;\n"
                 :: "r"(dst), "l"(src), "r"(sz));
}

__device__ __forceinline__ void mma_f16(float& d0, float& d1, float& d2, float& d3,
                                        uint32_t a0, uint32_t a1, uint32_t a2, uint32_t a3,
                                        uint32_t b0, uint32_t b1) {
    asm("mma.sync.aligned.m16n8k16.row.col.f32.f16.f16.f32 "
        "{%0,%1,%2,%3}, {%4,%5,%6,%7}, {%8,%9}, {%0,%1,%2,%3};"
        : "+f"(d0), "+f"(d1), "+f"(d2), "+f"(d3)
        : "r"(a0), "r"(a1), "r"(a2), "r"(a3), "r"(b0), "r"(b1));
}

__device__ __forceinline__ void ldmx4(uint32_t& r0, uint32_t& r1, uint32_t& r2, uint32_t& r3,
                                      uint32_t addr) {
    asm volatile("ldmatrix.sync.aligned.m8n8.x4.shared.b16 {%0,%1,%2,%3}, [%4];"
                 : "=r"(r0), "=r"(r1), "=r"(r2), "=r"(r3) : "r"(addr));
}

// device-wide barrier for the co-resident CSR kernel
__device__ __forceinline__ void gbar(int target_phase) {
    __syncthreads();
    if (threadIdx.x == 0) {
        __threadfence();
        if (atomicAdd(&g_gcnt, 1) == CSRB - 1) {
            g_gcnt = 0;
            __threadfence();
            g_gphase = target_phase;
        } else {
            while (g_gphase < target_phase) {}
        }
    }
    __syncthreads();
}

// ---------------------------------------------------------------
// fused prep: x->fp16 + W fp16 + deg zero + sentinels + ranges + out zero
#define PREP_X (HSZ / 4)
#define PREP_W (3 * KDIM * CC)
__global__ void k_prep(const float* __restrict__ x, const float* __restrict__ cw,
                       const int* __restrict__ batch, float* __restrict__ out) {
    int i = blockIdx.x * 256 + threadIdx.x;
    if (i < PREP_X) {
        float4 v = *reinterpret_cast<const float4*>(x + (size_t)i * 4);
        __half2* hb = reinterpret_cast<__half2*>(g_hb + (size_t)i * 4);
        hb[0] = __halves2half2(__float2half_rn(v.x), __float2half_rn(v.y));
        hb[1] = __halves2half2(__float2half_rn(v.z), __float2half_rn(v.w));
        return;
    }
    i -= PREP_X;
    if (i < PREP_W) {
        int n = i & 255;
        int k = (i >> 8) & 511;
        int l = i >> 17;
        g_wb[((size_t)l * CC + n) * KDIM + k] =
            __float2half_rn(cw[((size_t)l * KDIM + k) * CC + n]);
        return;
    }
    i -= PREP_W;
    if (i < NN) {
        g_degi[i] = 0;
        if (i < NB) g_bsum[i] = -1;
        if (i == 0) { g_gcnt = 0; g_gphase = 0; }
        int b = batch[i];
        if (i == 0 || batch[i - 1] != b) g_gstart[b] = i;
        if (i == NN - 1 || batch[i + 1] != b) g_gend[b] = i + 1;
        return;
    }
    i -= NN;
    if (i < OUTSZ) out[i] = 0.0f;
}

// ---------------------------------------------------------------
// fused CSR builder: deg -> barrier -> dis+scan -> barrier -> fill
__global__ __launch_bounds__(256, 1) void k_csr(const int* __restrict__ ei) {
    const int b = blockIdx.x, t = threadIdx.x;
    const int gt = b * 256 + t;
    const int NT = CSRB * 256;

    for (int e = gt; e < EE; e += NT)
        atomicAdd(&g_degi[ei[e]], 1);
    gbar(1);

    if (b < NB) {
        __shared__ int sm[256];
        __shared__ int red[8];
        const int i = b * 256 + t;
        int d = 0;
        if (i < NN) {
            d = g_degi[i];
            g_dis[i] = (d > 0) ? rsqrtf((float)d) : 0.0f;
        }
        sm[t] = d;
        __syncthreads();
#pragma unroll
        for (int off = 1; off < 256; off <<= 1) {
            int u = (t >= off) ? sm[t - off] : 0;
            __syncthreads();
            sm[t] += u;
            __syncthreads();
        }
        const int total = sm[255];
        const int local_ex = sm[t] - d;
        if (t == 0) {
            __threadfence();
            atomicExch(&g_bsum[b], total);
        }
        int pred = 0;
        if (t < b) {
            volatile int* vb = g_bsum;
            int v;
            do { v = vb[t]; } while (v < 0);
            pred = v;
        }
        int v = pred;
#pragma unroll
        for (int off = 16; off; off >>= 1) v += __shfl_down_sync(0xffffffffu, v, off);
        if ((t & 31) == 0) red[t >> 5] = v;
        __syncthreads();
        if (t < 8) {
            int s = red[t];
#pragma unroll
            for (int off = 4; off; off >>= 1) s += __shfl_down_sync(0xffu, s, off);
            if (t == 0) red[0] = s;
        }
        __syncthreads();
        const int base = red[0];
        if (i < NN) {
            g_rowptr[i] = base + local_ex;
            g_cnt[i]    = base + local_ex;
        }
        if (b == NB - 1 && t == 255) g_rowptr[NN] = base + total;
    }
    gbar(2);

    for (int e = gt; e < EE; e += NT) {
        int r = ei[e];
        int c = ei[e + EE];
        int pos = atomicAdd(&g_cnt[r], 1);
        g_ccol[pos] = c;
        g_cw[pos]   = -(g_dis[r] * g_dis[c]);
    }
}

// ---------------------------------------------------------------
// SpMM (fp16 input, 8-way unrolled MLP): p[v,:] = sum w * h16[col,:]; fp32 accum.
__global__ void k_spmm(int layer) {
    int w = (blockIdx.x * blockDim.x + threadIdx.x) >> 5;
    int lane = threadIdx.x & 31;
    if (w >= NN) return;
    const __half* hin = g_hb + (size_t)(layer & 1) * HSZ;

    float acc[8];
#pragma unroll
    for (int q = 0; q < 8; q++) acc[q] = 0.f;

    const int s = g_rowptr[w], e = g_rowptr[w + 1];
    int i = s;
    for (; i + 7 < e; i += 8) {
        uint4 rr[8];
        float ww[8];
#pragma unroll
        for (int j = 0; j < 8; j++) {
            int u = g_ccol[i + j];
            ww[j] = g_cw[i + j];
            rr[j] = __ldg(reinterpret_cast<const uint4*>(hin + (size_t)u * CC + lane * 8));
        }
#pragma unroll
        for (int j = 0; j < 8; j++) {
            const __half2* hp = reinterpret_cast<const __half2*>(&rr[j]);
#pragma unroll
            for (int q = 0; q < 4; q++) {
                float2 f = __half22float2(hp[q]);
                acc[2 * q]     += ww[j] * f.x;
                acc[2 * q + 1] += ww[j] * f.y;
            }
        }
    }
    for (; i < e; i++) {
        int u = g_ccol[i];
        float wt = g_cw[i];
        uint4 raw = __ldg(reinterpret_cast<const uint4*>(hin + (size_t)u * CC + lane * 8));
        const __half2* hp = reinterpret_cast<const __half2*>(&raw);
#pragma unroll
        for (int q = 0; q < 4; q++) {
            float2 f = __half22float2(hp[q]);
            acc[2 * q]     += wt * f.x;
            acc[2 * q + 1] += wt * f.y;
        }
    }
    size_t o = (size_t)w * CC + lane * 8;
    __half2* pb = reinterpret_cast<__half2*>(g_pb + o);
#pragma unroll
    for (int q = 0; q < 4; q++)
        pb[q] = __halves2half2(__float2half_rn(acc[2 * q]), __float2half_rn(acc[2 * q + 1]));
}

// ---------------------------------------------------------------
// Tile loader: A 128x32 fp16 + B 128x32 fp16, rows padded to 40 halves (80 B).
__device__ __forceinline__ void issue_tile(
    uint32_t sb, int stage, int kt, int m0, int n0,
    const __half* __restrict__ hb, const __half* __restrict__ wb, int tid)
{
    uint32_t base = sb + stage * STG_BYTES;
    int kbase = kt * 32;
    const __half* ab; int acol;
    if (kbase < CC) { ab = hb;   acol = kbase; }
    else            { ab = g_pb; acol = kbase - CC; }
#pragma unroll
    for (int rep = 0; rep < 2; rep++) {
        int idx = tid + rep * 256;       // 0..511
        int r   = idx >> 2;              // 0..127
        int ch  = idx & 3;
        int gr = m0 + r;
        int sz = (gr < NN) ? 16 : 0;
        if (gr >= NN) gr = NN - 1;
        cpa16(base + r * 80 + ch * 16,
              ab + (size_t)gr * CC + acol + ch * 8, sz);
    }
#pragma unroll
    for (int rep = 0; rep < 2; rep++) {
        int idx = tid + rep * 256;       // 0..511
        int r   = idx >> 2;
        int ch  = idx & 3;
        cpa16(base + 10240 + r * 80 + ch * 16,
              wb + (size_t)(n0 + r) * KDIM + kbase + ch * 8, 16);
    }
}

// ---------------------------------------------------------------
// fp16 GEMM, BM=128 BN=128, 256 thr, 8 warps 2m x 4n, 4-stage pipe.
// cp.async.cg (L1-bypass); prefetch issued AFTER compute; batched LDSM.
// Fused BN/ReLU + next-layer fp16 store + graph-mean-pool accumulation.
__global__ __launch_bounds__(256, 2) void k_gemm(
    const float* __restrict__ gamma,
    const float* __restrict__ beta,
    float* __restrict__ out,
    int layer)
{
    extern __shared__ char smc[];
    uint32_t sb = smem_u32(smc);
    const int tid = threadIdx.x;
    const int wid = tid >> 5, lane = tid & 31;
    const int wm = wid >> 2, wn = wid & 3;
    const int gid = lane >> 2, tig = lane & 3;
    const int lrow = lane & 7, grp = lane >> 3;
    const int m0 = blockIdx.x * 128;
    const int n0 = blockIdx.y * 128;

    const __half* hb = g_hb + (size_t)(layer & 1) * HSZ;
    const __half* wb = g_wb + (size_t)layer * CC * KDIM;

    float acc[4][4][4];
#pragma unroll
    for (int mi = 0; mi < 4; mi++)
#pragma unroll
        for (int ni = 0; ni < 4; ni++)
#pragma unroll
            for (int r = 0; r < 4; r++) acc[mi][ni][r] = 0.f;

    const uint32_t a_row = (uint32_t)(wm * 64 + ((grp & 1) << 3) + lrow) * 80;
    const uint32_t a_kof = (uint32_t)((grp >> 1) << 3) * 2;
    const uint32_t b_row = (uint32_t)(wn * 32 + ((grp >> 1) << 3) + lrow) * 80;
    const uint32_t b_kof = (uint32_t)((grp & 1) << 3) * 2;

    issue_tile(sb, 0, 0, m0, n0, hb, wb, tid);
    asm volatile("cp.async.commit_group;");
    issue_tile(sb, 1, 1, m0, n0, hb, wb, tid);
    asm volatile("cp.async.commit_group;");
    issue_tile(sb, 2, 2, m0, n0, hb, wb, tid);
    asm volatile("cp.async.commit_group;");

    int stage = 0;
    for (int kt = 0; kt < 16; kt++) {
        if (kt < 14)      { asm volatile("cp.async.wait_group 2;"); }
        else if (kt == 14){ asm volatile("cp.async.wait_group 1;"); }
        else              { asm volatile("cp.async.wait_group 0;"); }
        __syncthreads();

        const uint32_t stg = sb + stage * STG_BYTES;
#pragma unroll
        for (int ks = 0; ks < 2; ks++) {
            const uint32_t kk2 = (uint32_t)(ks * 16) * 2;
            uint32_t bb[4][2];
            uint32_t aa[4][4];
#pragma unroll
            for (int np = 0; np < 2; np++) {
                uint32_t baddr = stg + 10240 + np * 16 * 80 + b_row + kk2 + b_kof;
                ldmx4(bb[2 * np][0], bb[2 * np][1], bb[2 * np + 1][0], bb[2 * np + 1][1], baddr);
            }
#pragma unroll
            for (int mi = 0; mi < 4; mi++) {
                uint32_t aaddr = stg + mi * 16 * 80 + a_row + kk2 + a_kof;
                ldmx4(aa[mi][0], aa[mi][1], aa[mi][2], aa[mi][3], aaddr);
            }
#pragma unroll
            for (int mi = 0; mi < 4; mi++)
#pragma unroll
                for (int ni = 0; ni < 4; ni++)
                    mma_f16(acc[mi][ni][0], acc[mi][ni][1], acc[mi][ni][2], acc[mi][ni][3],
                            aa[mi][0], aa[mi][1], aa[mi][2], aa[mi][3],
                            bb[ni][0], bb[ni][1]);
        }
        // prefetch AFTER compute: LDGSTS issue overlaps accumulator drain
        if (kt + 3 < 16) {
            int nstage = stage + 3; if (nstage >= NSTG) nstage -= NSTG;
            issue_tile(sb, nstage, kt + 3, m0, n0, hb, wb, tid);
            asm volatile("cp.async.commit_group;");
        }
        if (++stage >= NSTG) stage -= NSTG;
    }

    // epilogue: BN/ReLU -> next-layer fp16 (layers 0,1) + fused pool sums.
    const float inv = rsqrtf(1.0f + 1e-5f);
    __half* ob = g_hb + (size_t)((layer + 1) & 1) * HSZ;
    const bool wr_next = (layer < 2);
    const int gbase = m0 / 400;
#pragma unroll
    for (int ni = 0; ni < 4; ni++) {
        int c = n0 + wn * 32 + ni * 8 + 2 * tig;
        float s0 = __ldg(&gamma[layer * CC + c])     * inv;
        float s1 = __ldg(&gamma[layer * CC + c + 1]) * inv;
        float b0 = __ldg(&beta[layer * CC + c]);
        float b1 = __ldg(&beta[layer * CC + c + 1]);
        float ps[2][2] = {{0.f, 0.f}, {0.f, 0.f}};
#pragma unroll
        for (int mi = 0; mi < 4; mi++) {
            int r0 = m0 + wm * 64 + mi * 16 + gid;
            int r1 = r0 + 8;
            float v0 = acc[mi][ni][0], v1 = acc[mi][ni][1];
            float v2 = acc[mi][ni][2], v3 = acc[mi][ni][3];
            float o0, o1, o2, o3;
            if (layer == 0) {
                o0 = fmaxf(v0 * s0 + b0, 0.f); o1 = fmaxf(v1 * s1 + b1, 0.f);
                o2 = fmaxf(v2 * s0 + b0, 0.f); o3 = fmaxf(v3 * s1 + b1, 0.f);
            } else {
                o0 = fmaxf(v0, 0.f) * s0 + b0; o1 = fmaxf(v1, 0.f) * s1 + b1;
                o2 = fmaxf(v2, 0.f) * s0 + b0; o3 = fmaxf(v3, 0.f) * s1 + b1;
            }
            if (r0 < NN) {
                int sg = r0 / 400 - gbase;
                ps[sg][0] += o0; ps[sg][1] += o1;
                if (wr_next)
                    *reinterpret_cast<__half2*>(&ob[(size_t)r0 * CC + c]) =
                        __halves2half2(__float2half_rn(o0), __float2half_rn(o1));
            }
            if (r1 < NN) {
                int sg = r1 / 400 - gbase;
                ps[sg][0] += o2; ps[sg][1] += o3;
                if (wr_next)
                    *reinterpret_cast<__half2*>(&ob[(size_t)r1 * CC + c]) =
                        __halves2half2(__float2half_rn(o2), __float2half_rn(o3));
            }
        }
#pragma unroll
        for (int sg = 0; sg < 2; sg++) {
#pragma unroll
            for (int cp = 0; cp < 2; cp++) {
                float v = ps[sg][cp];
                v += __shfl_down_sync(0xffffffffu, v, 16);
                v += __shfl_down_sync(0xffffffffu, v, 8);
                v += __shfl_down_sync(0xffffffffu, v, 4);
                if (lane < 4) {
                    int g = gbase + sg;
                    if (g < GG)
                        atomicAdd(&out[(size_t)g * JKW + layer * CC + c + cp], v);
                }
            }
        }
    }
}

// ---------------------------------------------------------------
// classifier: divide pool sums -> write mean -> Linear/ReLU/BN/Linear
__global__ void k_cls(const float* __restrict__ W1, const float* __restrict__ b1,
                      const float* __restrict__ cg, const float* __restrict__ cbe,
                      const float* __restrict__ W2, const float* __restrict__ b2,
                      float* __restrict__ out)
{
    __shared__ float zr[JKW];
    __shared__ float zz[256];
    int g = blockIdx.x, t = threadIdx.x;
    float rc = 1.0f / (float)(g_gend[g] - g_gstart[g]);
    for (int j = t; j < JKW; j += 256) {
        float v = out[(size_t)g * JKW + j] * rc;
        zr[j] = v;
        out[(size_t)g * JKW + j] = v;
    }
    __syncthreads();

    float acc = b1[t];
    const float* w = W1 + (size_t)t * JKW;
    for (int j = 0; j < JKW; j++) acc += zr[j] * w[j];
    const float inv = rsqrtf(1.0f + 1e-5f);
    zz[t] = fmaxf(acc, 0.f) * cg[t] * inv + cbe[t];
    __syncthreads();

    if (t < 64) {
        int k = t >> 5;
        int lane = t & 31;
        float s = 0.f;
        for (int o = lane; o < 256; o += 32) s += zz[o] * W2[k * 256 + o];
#pragma unroll
        for (int off = 16; off; off >>= 1) s += __shfl_down_sync(0xffffffffu, s, off);
        if (lane == 0) out[GG * JKW + g * 2 + k] = s + b2[k];
    }
}

// ---------------------------------------------------------------
extern "C" void kernel_launch(void* const* d_in, const int* in_sizes, int n_in,
                              void* d_out, int out_size)
{
    const float* x    = (const float*)d_in[0];
    const int*   ei   = (const int*)  d_in[1];
    const int*   batch= (const int*)  d_in[2];
    const float* cw   = (const float*)d_in[3];
    const float* bg   = (const float*)d_in[4];
    const float* bb   = (const float*)d_in[5];
    const float* w1   = (const float*)d_in[6];
    const float* b1   = (const float*)d_in[7];
    const float* cg   = (const float*)d_in[8];
    const float* cbe  = (const float*)d_in[9];
    const float* w2   = (const float*)d_in[10];
    const float* b2   = (const float*)d_in[11];
    float* out = (float*)d_out;

    cudaFuncSetAttribute(k_gemm, cudaFuncAttributeMaxDynamicSharedMemorySize, SMEM_TOT);

    int prep_total = PREP_X + PREP_W + NN + OUTSZ;
    k_prep<<<(prep_total + 255) / 256, 256>>>(x, cw, batch, out);
    k_csr<<<CSRB, 256>>>(ei);

    for (int l = 0; l < 3; l++) {
        k_spmm<<<(NN + 7) / 8, 256>>>(l);
        dim3 grid((NN + 127) / 128, 2);
        k_gemm<<<grid, 256, SMEM_TOT>>>(bg, bb, out, l);
    }

    k_cls<<<GG, 256>>>(w1, b1, cg, cbe, w2, b2, out);
}

// round 13
// speedup vs baseline: 1.0337x; 1.0337x over previous
#include <cuda_runtime.h>
#include <cuda_fp16.h>
#include <cstdint>

#define NN 20000
#define EE 320000
#define CC 256
#define GG 50
#define JKW 768
#define KDIM 512
#define HSZ (NN * CC)
#define NB 79                     // ceil(20000/256) scan blocks
#define CSRB 148                  // CSR builder blocks (1/SM, co-resident)
#define OUTSZ (GG * JKW + GG * 2) // 38500

#define STG_BYTES 20480          // A 10240 | B 10240
#define NSTG 4
#define SMEM_TOT (NSTG * STG_BYTES) // 80 KB, quad buffered

// ---- scratch (static device globals; no runtime allocation) ----
__device__ int   g_degi[NN];
__device__ int   g_cnt[NN];
__device__ float g_dis[NN];
__device__ int   g_rowptr[NN + 1];
__device__ int   g_bsum[NB];
__device__ int   g_gcnt;
__device__ volatile int g_gphase;
__device__ int   g_ccol[EE];
__device__ float g_cw[EE];
__device__ __align__(16) __half g_hb[2 * HSZ];      // h fp16, ping-pong by layer
__device__ __align__(16) __half g_pb[HSZ];          // p fp16
__device__ __align__(16) __half g_wb[3 * CC * KDIM];// W^T fp16 [l][n][k]
__device__ int   g_gstart[GG];
__device__ int   g_gend[GG];

// ---------------- helpers ----------------
__device__ __forceinline__ uint32_t smem_u32(const void* p) {
    uint32_t a;
    asm("{ .reg .u64 t; cvta.to.shared.u64 t, %1; cvt.u32.u64 %0, t; }" : "=r"(a) : "l"(p));
    return a;
}

// L1-bypassing bulk async copy
__device__ __forceinline__ void cpa16(uint32_t dst, const void* src, int sz) {
    asm volatile("cp.async.cg.shared.global [%0], [%1], 16, %2;\n"
                 :: "r"(dst), "l"(src), "r"(sz));
}

__device__ __forceinline__ void mma_f16(float& d0, float& d1, float& d2, float& d3,
                                        uint32_t a0, uint32_t a1, uint32_t a2, uint32_t a3,
                                        uint32_t b0, uint32_t b1) {
    asm("mma.sync.aligned.m16n8k16.row.col.f32.f16.f16.f32 "
        "{%0,%1,%2,%3}, {%4,%5,%6,%7}, {%8,%9}, {%0,%1,%2,%3};"
        : "+f"(d0), "+f"(d1), "+f"(d2), "+f"(d3)
        : "r"(a0), "r"(a1), "r"(a2), "r"(a3), "r"(b0), "r"(b1));
}

__device__ __forceinline__ void ldmx4(uint32_t& r0, uint32_t& r1, uint32_t& r2, uint32_t& r3,
                                      uint32_t addr) {
    asm volatile("ldmatrix.sync.aligned.m8n8.x4.shared.b16 {%0,%1,%2,%3}, [%4];"
                 : "=r"(r0), "=r"(r1), "=r"(r2), "=r"(r3) : "r"(addr));
}

// device-wide barrier for the co-resident CSR kernel
__device__ __forceinline__ void gbar(int target_phase) {
    __syncthreads();
    if (threadIdx.x == 0) {
        __threadfence();
        if (atomicAdd(&g_gcnt, 1) == CSRB - 1) {
            g_gcnt = 0;
            __threadfence();
            g_gphase = target_phase;
        } else {
            while (g_gphase < target_phase) {}
        }
    }
    __syncthreads();
}

// ---------------------------------------------------------------
// fused prep: x->fp16 + W fp16 + deg zero + sentinels + ranges + out zero
#define PREP_X (HSZ / 4)
#define PREP_W (3 * KDIM * CC)
__global__ void k_prep(const float* __restrict__ x, const float* __restrict__ cw,
                       const int* __restrict__ batch, float* __restrict__ out) {
    int i = blockIdx.x * 256 + threadIdx.x;
    if (i < PREP_X) {
        float4 v = *reinterpret_cast<const float4*>(x + (size_t)i * 4);
        __half2* hb = reinterpret_cast<__half2*>(g_hb + (size_t)i * 4);
        hb[0] = __halves2half2(__float2half_rn(v.x), __float2half_rn(v.y));
        hb[1] = __halves2half2(__float2half_rn(v.z), __float2half_rn(v.w));
        return;
    }
    i -= PREP_X;
    if (i < PREP_W) {
        int n = i & 255;
        int k = (i >> 8) & 511;
        int l = i >> 17;
        g_wb[((size_t)l * CC + n) * KDIM + k] =
            __float2half_rn(cw[((size_t)l * KDIM + k) * CC + n]);
        return;
    }
    i -= PREP_W;
    if (i < NN) {
        g_degi[i] = 0;
        if (i < NB) g_bsum[i] = -1;
        if (i == 0) { g_gcnt = 0; g_gphase = 0; }
        int b = batch[i];
        if (i == 0 || batch[i - 1] != b) g_gstart[b] = i;
        if (i == NN - 1 || batch[i + 1] != b) g_gend[b] = i + 1;
        return;
    }
    i -= NN;
    if (i < OUTSZ) out[i] = 0.0f;
}

// ---------------------------------------------------------------
// fused CSR builder: deg -> barrier -> dis+scan -> barrier -> fill
__global__ __launch_bounds__(256, 1) void k_csr(const int* __restrict__ ei) {
    const int b = blockIdx.x, t = threadIdx.x;
    const int gt = b * 256 + t;
    const int NT = CSRB * 256;

    for (int e = gt; e < EE; e += NT)
        atomicAdd(&g_degi[ei[e]], 1);
    gbar(1);

    if (b < NB) {
        __shared__ int sm[256];
        __shared__ int red[8];
        const int i = b * 256 + t;
        int d = 0;
        if (i < NN) {
            d = g_degi[i];
            g_dis[i] = (d > 0) ? rsqrtf((float)d) : 0.0f;
        }
        sm[t] = d;
        __syncthreads();
#pragma unroll
        for (int off = 1; off < 256; off <<= 1) {
            int u = (t >= off) ? sm[t - off] : 0;
            __syncthreads();
            sm[t] += u;
            __syncthreads();
        }
        const int total = sm[255];
        const int local_ex = sm[t] - d;
        if (t == 0) {
            __threadfence();
            atomicExch(&g_bsum[b], total);
        }
        int pred = 0;
        if (t < b) {
            volatile int* vb = g_bsum;
            int v;
            do { v = vb[t]; } while (v < 0);
            pred = v;
        }
        int v = pred;
#pragma unroll
        for (int off = 16; off; off >>= 1) v += __shfl_down_sync(0xffffffffu, v, off);
        if ((t & 31) == 0) red[t >> 5] = v;
        __syncthreads();
        if (t < 8) {
            int s = red[t];
#pragma unroll
            for (int off = 4; off; off >>= 1) s += __shfl_down_sync(0xffu, s, off);
            if (t == 0) red[0] = s;
        }
        __syncthreads();
        const int base = red[0];
        if (i < NN) {
            g_rowptr[i] = base + local_ex;
            g_cnt[i]    = base + local_ex;
        }
        if (b == NB - 1 && t == 255) g_rowptr[NN] = base + total;
    }
    gbar(2);

    for (int e = gt; e < EE; e += NT) {
        int r = ei[e];
        int c = ei[e + EE];
        int pos = atomicAdd(&g_cnt[r], 1);
        g_ccol[pos] = c;
        g_cw[pos]   = -(g_dis[r] * g_dis[c]);
    }
}

// ---------------------------------------------------------------
// SpMM (fp16 input, 4-way unrolled): p[v,:] = sum w * h16[col,:]; fp32 accum.
__global__ void k_spmm(int layer) {
    int w = (blockIdx.x * blockDim.x + threadIdx.x) >> 5;
    int lane = threadIdx.x & 31;
    if (w >= NN) return;
    const __half* hin = g_hb + (size_t)(layer & 1) * HSZ;

    float acc[8];
#pragma unroll
    for (int q = 0; q < 8; q++) acc[q] = 0.f;

    const int s = g_rowptr[w], e = g_rowptr[w + 1];
    int i = s;
    for (; i + 3 < e; i += 4) {
        int u0 = g_ccol[i], u1 = g_ccol[i + 1], u2 = g_ccol[i + 2], u3 = g_ccol[i + 3];
        float w0 = g_cw[i], w1 = g_cw[i + 1], w2 = g_cw[i + 2], w3 = g_cw[i + 3];
        uint4 r0 = __ldg(reinterpret_cast<const uint4*>(hin + (size_t)u0 * CC + lane * 8));
        uint4 r1 = __ldg(reinterpret_cast<const uint4*>(hin + (size_t)u1 * CC + lane * 8));
        uint4 r2 = __ldg(reinterpret_cast<const uint4*>(hin + (size_t)u2 * CC + lane * 8));
        uint4 r3 = __ldg(reinterpret_cast<const uint4*>(hin + (size_t)u3 * CC + lane * 8));
        const __half2* h0 = reinterpret_cast<const __half2*>(&r0);
        const __half2* h1 = reinterpret_cast<const __half2*>(&r1);
        const __half2* h2 = reinterpret_cast<const __half2*>(&r2);
        const __half2* h3 = reinterpret_cast<const __half2*>(&r3);
#pragma unroll
        for (int q = 0; q < 4; q++) {
            float2 f0 = __half22float2(h0[q]);
            float2 f1 = __half22float2(h1[q]);
            float2 f2 = __half22float2(h2[q]);
            float2 f3 = __half22float2(h3[q]);
            acc[2 * q]     += w0 * f0.x + w1 * f1.x + w2 * f2.x + w3 * f3.x;
            acc[2 * q + 1] += w0 * f0.y + w1 * f1.y + w2 * f2.y + w3 * f3.y;
        }
    }
    for (; i < e; i++) {
        int u = g_ccol[i];
        float wt = g_cw[i];
        uint4 raw = __ldg(reinterpret_cast<const uint4*>(hin + (size_t)u * CC + lane * 8));
        const __half2* hp = reinterpret_cast<const __half2*>(&raw);
#pragma unroll
        for (int q = 0; q < 4; q++) {
            float2 f = __half22float2(hp[q]);
            acc[2 * q]     += wt * f.x;
            acc[2 * q + 1] += wt * f.y;
        }
    }
    size_t o = (size_t)w * CC + lane * 8;
    __half2* pb = reinterpret_cast<__half2*>(g_pb + o);
#pragma unroll
    for (int q = 0; q < 4; q++)
        pb[q] = __halves2half2(__float2half_rn(acc[2 * q]), __float2half_rn(acc[2 * q + 1]));
}

// ---------------------------------------------------------------
// Tile loader (512 threads): A 128x32 fp16 + B 128x32 fp16, 80 B row pitch.
__device__ __forceinline__ void issue_tile(
    uint32_t sb, int stage, int kt, int m0, int n0,
    const __half* __restrict__ hb, const __half* __restrict__ wb, int tid)
{
    uint32_t base = sb + stage * STG_BYTES;
    int kbase = kt * 32;
    const __half* ab; int acol;
    if (kbase < CC) { ab = hb;   acol = kbase; }
    else            { ab = g_pb; acol = kbase - CC; }
    {
        int r  = tid >> 2;               // 0..127
        int ch = tid & 3;
        int gr = m0 + r;
        int sz = (gr < NN) ? 16 : 0;
        if (gr >= NN) gr = NN - 1;
        cpa16(base + r * 80 + ch * 16,
              ab + (size_t)gr * CC + acol + ch * 8, sz);
    }
    {
        int r  = tid >> 2;
        int ch = tid & 3;
        cpa16(base + 10240 + r * 80 + ch * 16,
              wb + (size_t)(n0 + r) * KDIM + kbase + ch * 8, 16);
    }
}

// ---------------------------------------------------------------
// fp16 GEMM, BM=128 BN=128, 512 thr, 16 warps 4m x 4n (warp tile 32x32),
// 2 CTAs/SM -> 32 warps/SM. cp.async.cg, 4-stage pipe, batched LDSM.
// Fused BN/ReLU + next-layer fp16 store + graph-mean-pool accumulation.
__global__ __launch_bounds__(512, 2) void k_gemm(
    const float* __restrict__ gamma,
    const float* __restrict__ beta,
    float* __restrict__ out,
    int layer)
{
    extern __shared__ char smc[];
    uint32_t sb = smem_u32(smc);
    const int tid = threadIdx.x;
    const int wid = tid >> 5, lane = tid & 31;
    const int wm = wid >> 2, wn = wid & 3;       // 4 x 4 warps
    const int gid = lane >> 2, tig = lane & 3;
    const int lrow = lane & 7, grp = lane >> 3;
    const int m0 = blockIdx.x * 128;
    const int n0 = blockIdx.y * 128;

    const __half* hb = g_hb + (size_t)(layer & 1) * HSZ;
    const __half* wb = g_wb + (size_t)layer * CC * KDIM;

    float acc[2][4][4];
#pragma unroll
    for (int mi = 0; mi < 2; mi++)
#pragma unroll
        for (int ni = 0; ni < 4; ni++)
#pragma unroll
            for (int r = 0; r < 4; r++) acc[mi][ni][r] = 0.f;

    const uint32_t a_row = (uint32_t)(wm * 32 + ((grp & 1) << 3) + lrow) * 80;
    const uint32_t a_kof = (uint32_t)((grp >> 1) << 3) * 2;
    const uint32_t b_row = (uint32_t)(wn * 32 + ((grp >> 1) << 3) + lrow) * 80;
    const uint32_t b_kof = (uint32_t)((grp & 1) << 3) * 2;

    issue_tile(sb, 0, 0, m0, n0, hb, wb, tid);
    asm volatile("cp.async.commit_group;");
    issue_tile(sb, 1, 1, m0, n0, hb, wb, tid);
    asm volatile("cp.async.commit_group;");
    issue_tile(sb, 2, 2, m0, n0, hb, wb, tid);
    asm volatile("cp.async.commit_group;");

    int stage = 0;
    for (int kt = 0; kt < 16; kt++) {
        if (kt < 14)      { asm volatile("cp.async.wait_group 2;"); }
        else if (kt == 14){ asm volatile("cp.async.wait_group 1;"); }
        else              { asm volatile("cp.async.wait_group 0;"); }
        __syncthreads();

        const uint32_t stg = sb + stage * STG_BYTES;
#pragma unroll
        for (int ks = 0; ks < 2; ks++) {
            const uint32_t kk2 = (uint32_t)(ks * 16) * 2;
            uint32_t bb[4][2];
            uint32_t aa[2][4];
#pragma unroll
            for (int np = 0; np < 2; np++) {
                uint32_t baddr = stg + 10240 + np * 16 * 80 + b_row + kk2 + b_kof;
                ldmx4(bb[2 * np][0], bb[2 * np][1], bb[2 * np + 1][0], bb[2 * np + 1][1], baddr);
            }
#pragma unroll
            for (int mi = 0; mi < 2; mi++) {
                uint32_t aaddr = stg + mi * 16 * 80 + a_row + kk2 + a_kof;
                ldmx4(aa[mi][0], aa[mi][1], aa[mi][2], aa[mi][3], aaddr);
            }
#pragma unroll
            for (int mi = 0; mi < 2; mi++)
#pragma unroll
                for (int ni = 0; ni < 4; ni++)
                    mma_f16(acc[mi][ni][0], acc[mi][ni][1], acc[mi][ni][2], acc[mi][ni][3],
                            aa[mi][0], aa[mi][1], aa[mi][2], aa[mi][3],
                            bb[ni][0], bb[ni][1]);
        }
        if (kt + 3 < 16) {
            int nstage = stage + 3; if (nstage >= NSTG) nstage -= NSTG;
            issue_tile(sb, nstage, kt + 3, m0, n0, hb, wb, tid);
            asm volatile("cp.async.commit_group;");
        }
        if (++stage >= NSTG) stage -= NSTG;
    }

    // epilogue: BN/ReLU -> next-layer fp16 (layers 0,1) + fused pool sums.
    const float inv = rsqrtf(1.0f + 1e-5f);
    __half* ob = g_hb + (size_t)((layer + 1) & 1) * HSZ;
    const bool wr_next = (layer < 2);
    const int gbase = m0 / 400;
#pragma unroll
    for (int ni = 0; ni < 4; ni++) {
        int c = n0 + wn * 32 + ni * 8 + 2 * tig;
        float s0 = __ldg(&gamma[layer * CC + c])     * inv;
        float s1 = __ldg(&gamma[layer * CC + c + 1]) * inv;
        float b0 = __ldg(&beta[layer * CC + c]);
        float b1 = __ldg(&beta[layer * CC + c + 1]);
        float ps[2][2] = {{0.f, 0.f}, {0.f, 0.f}};
#pragma unroll
        for (int mi = 0; mi < 2; mi++) {
            int r0 = m0 + wm * 32 + mi * 16 + gid;
            int r1 = r0 + 8;
            float v0 = acc[mi][ni][0], v1 = acc[mi][ni][1];
            float v2 = acc[mi][ni][2], v3 = acc[mi][ni][3];
            float o0, o1, o2, o3;
            if (layer == 0) {
                o0 = fmaxf(v0 * s0 + b0, 0.f); o1 = fmaxf(v1 * s1 + b1, 0.f);
                o2 = fmaxf(v2 * s0 + b0, 0.f); o3 = fmaxf(v3 * s1 + b1, 0.f);
            } else {
                o0 = fmaxf(v0, 0.f) * s0 + b0; o1 = fmaxf(v1, 0.f) * s1 + b1;
                o2 = fmaxf(v2, 0.f) * s0 + b0; o3 = fmaxf(v3, 0.f) * s1 + b1;
            }
            if (r0 < NN) {
                int sg = r0 / 400 - gbase;
                ps[sg][0] += o0; ps[sg][1] += o1;
                if (wr_next)
                    *reinterpret_cast<__half2*>(&ob[(size_t)r0 * CC + c]) =
                        __halves2half2(__float2half_rn(o0), __float2half_rn(o1));
            }
            if (r1 < NN) {
                int sg = r1 / 400 - gbase;
                ps[sg][0] += o2; ps[sg][1] += o3;
                if (wr_next)
                    *reinterpret_cast<__half2*>(&ob[(size_t)r1 * CC + c]) =
                        __halves2half2(__float2half_rn(o2), __float2half_rn(o3));
            }
        }
#pragma unroll
        for (int sg = 0; sg < 2; sg++) {
#pragma unroll
            for (int cp = 0; cp < 2; cp++) {
                float v = ps[sg][cp];
                v += __shfl_down_sync(0xffffffffu, v, 16);
                v += __shfl_down_sync(0xffffffffu, v, 8);
                v += __shfl_down_sync(0xffffffffu, v, 4);
                if (lane < 4) {
                    int g = gbase + sg;
                    if (g < GG)
                        atomicAdd(&out[(size_t)g * JKW + layer * CC + c + cp], v);
                }
            }
        }
    }
}

// ---------------------------------------------------------------
// classifier: divide pool sums -> write mean -> Linear/ReLU/BN/Linear
__global__ void k_cls(const float* __restrict__ W1, const float* __restrict__ b1,
                      const float* __restrict__ cg, const float* __restrict__ cbe,
                      const float* __restrict__ W2, const float* __restrict__ b2,
                      float* __restrict__ out)
{
    __shared__ float zr[JKW];
    __shared__ float zz[256];
    int g = blockIdx.x, t = threadIdx.x;
    float rc = 1.0f / (float)(g_gend[g] - g_gstart[g]);
    for (int j = t; j < JKW; j += 256) {
        float v = out[(size_t)g * JKW + j] * rc;
        zr[j] = v;
        out[(size_t)g * JKW + j] = v;
    }
    __syncthreads();

    float acc = b1[t];
    const float* w = W1 + (size_t)t * JKW;
    for (int j = 0; j < JKW; j++) acc += zr[j] * w[j];
    const float inv = rsqrtf(1.0f + 1e-5f);
    zz[t] = fmaxf(acc, 0.f) * cg[t] * inv + cbe[t];
    __syncthreads();

    if (t < 64) {
        int k = t >> 5;
        int lane = t & 31;
        float s = 0.f;
        for (int o = lane; o < 256; o += 32) s += zz[o] * W2[k * 256 + o];
#pragma unroll
        for (int off = 16; off; off >>= 1) s += __shfl_down_sync(0xffffffffu, s, off);
        if (lane == 0) out[GG * JKW + g * 2 + k] = s + b2[k];
    }
}

// ---------------------------------------------------------------
extern "C" void kernel_launch(void* const* d_in, const int* in_sizes, int n_in,
                              void* d_out, int out_size)
{
    const float* x    = (const float*)d_in[0];
    const int*   ei   = (const int*)  d_in[1];
    const int*   batch= (const int*)  d_in[2];
    const float* cw   = (const float*)d_in[3];
    const float* bg   = (const float*)d_in[4];
    const float* bb   = (const float*)d_in[5];
    const float* w1   = (const float*)d_in[6];
    const float* b1   = (const float*)d_in[7];
    const float* cg   = (const float*)d_in[8];
    const float* cbe  = (const float*)d_in[9];
    const float* w2   = (const float*)d_in[10];
    const float* b2   = (const float*)d_in[11];
    float* out = (float*)d_out;

    cudaFuncSetAttribute(k_gemm, cudaFuncAttributeMaxDynamicSharedMemorySize, SMEM_TOT);

    int prep_total = PREP_X + PREP_W + NN + OUTSZ;
    k_prep<<<(prep_total + 255) / 256, 256>>>(x, cw, batch, out);
    k_csr<<<CSRB, 256>>>(ei);

    for (int l = 0; l < 3; l++) {
        k_spmm<<<(NN + 7) / 8, 256>>>(l);
        dim3 grid((NN + 127) / 128, 2);
        k_gemm<<<grid, 512, SMEM_TOT>>>(bg, bb, out, l);
    }

    k_cls<<<GG, 256>>>(w1, b1, cg, cbe, w2, b2, out);
}

// round 14
// speedup vs baseline: 1.0411x; 1.0072x over previous
#include <cuda_runtime.h>
#include <cuda_fp16.h>
#include <cstdint>

#define NN 20000
#define EE 320000
#define CC 256
#define GG 50
#define JKW 768
#define KDIM 512
#define HSZ (NN * CC)
#define NB 79                     // ceil(20000/256) scan blocks
#define CSRB 148                  // CSR builder blocks (1/SM, co-resident)
#define OUTSZ (GG * JKW + GG * 2) // 38500

#define APITCH 144               // 64 halves (128 B) + 16 B pad
#define STG_A  (128 * APITCH)    // 18432
#define STG_BYTES (2 * STG_A)    // 36864: A | B
#define NSTG 2
#define SMEM_TOT (NSTG * STG_BYTES) // 73728 B/CTA, 2 CTAs/SM

// ---- scratch (static device globals; no runtime allocation) ----
__device__ int   g_degi[NN];
__device__ int   g_cnt[NN];
__device__ float g_dis[NN];
__device__ int   g_rowptr[NN + 1];
__device__ int   g_bsum[NB];
__device__ int   g_gcnt;
__device__ volatile int g_gphase;
__device__ int   g_ccol[EE];
__device__ float g_cw[EE];
__device__ __align__(16) __half g_hb[2 * HSZ];      // h fp16, ping-pong by layer
__device__ __align__(16) __half g_pb[HSZ];          // p fp16
__device__ __align__(16) __half g_wb[3 * CC * KDIM];// W^T fp16 [l][n][k]
__device__ int   g_gstart[GG];
__device__ int   g_gend[GG];

// ---------------- helpers ----------------
__device__ __forceinline__ uint32_t smem_u32(const void* p) {
    uint32_t a;
    asm("{ .reg .u64 t; cvta.to.shared.u64 t, %1; cvt.u32.u64 %0, t; }" : "=r"(a) : "l"(p));
    return a;
}

// L1-bypassing bulk async copy
__device__ __forceinline__ void cpa16(uint32_t dst, const void* src, int sz) {
    asm volatile("cp.async.cg.shared.global [%0], [%1], 16, %2;\n"
                 :: "r"(dst), "l"(src), "r"(sz));
}

__device__ __forceinline__ void mma_f16(float& d0, float& d1, float& d2, float& d3,
                                        uint32_t a0, uint32_t a1, uint32_t a2, uint32_t a3,
                                        uint32_t b0, uint32_t b1) {
    asm("mma.sync.aligned.m16n8k16.row.col.f32.f16.f16.f32 "
        "{%0,%1,%2,%3}, {%4,%5,%6,%7}, {%8,%9}, {%0,%1,%2,%3};"
        : "+f"(d0), "+f"(d1), "+f"(d2), "+f"(d3)
        : "r"(a0), "r"(a1), "r"(a2), "r"(a3), "r"(b0), "r"(b1));
}

__device__ __forceinline__ void ldmx4(uint32_t& r0, uint32_t& r1, uint32_t& r2, uint32_t& r3,
                                      uint32_t addr) {
    asm volatile("ldmatrix.sync.aligned.m8n8.x4.shared.b16 {%0,%1,%2,%3}, [%4];"
                 : "=r"(r0), "=r"(r1), "=r"(r2), "=r"(r3) : "r"(addr));
}

// device-wide barrier for the co-resident CSR kernel
__device__ __forceinline__ void gbar(int target_phase) {
    __syncthreads();
    if (threadIdx.x == 0) {
        __threadfence();
        if (atomicAdd(&g_gcnt, 1) == CSRB - 1) {
            g_gcnt = 0;
            __threadfence();
            g_gphase = target_phase;
        } else {
            while (g_gphase < target_phase) {}
        }
    }
    __syncthreads();
}

// ---------------------------------------------------------------
// fused prep: x->fp16 + W fp16 + deg zero + sentinels + ranges + out zero
#define PREP_X (HSZ / 4)
#define PREP_W (3 * KDIM * CC)
__global__ void k_prep(const float* __restrict__ x, const float* __restrict__ cw,
                       const int* __restrict__ batch, float* __restrict__ out) {
    int i = blockIdx.x * 256 + threadIdx.x;
    if (i < PREP_X) {
        float4 v = *reinterpret_cast<const float4*>(x + (size_t)i * 4);
        __half2* hb = reinterpret_cast<__half2*>(g_hb + (size_t)i * 4);
        hb[0] = __halves2half2(__float2half_rn(v.x), __float2half_rn(v.y));
        hb[1] = __halves2half2(__float2half_rn(v.z), __float2half_rn(v.w));
        return;
    }
    i -= PREP_X;
    if (i < PREP_W) {
        int n = i & 255;
        int k = (i >> 8) & 511;
        int l = i >> 17;
        g_wb[((size_t)l * CC + n) * KDIM + k] =
            __float2half_rn(cw[((size_t)l * KDIM + k) * CC + n]);
        return;
    }
    i -= PREP_W;
    if (i < NN) {
        g_degi[i] = 0;
        if (i < NB) g_bsum[i] = -1;
        if (i == 0) { g_gcnt = 0; g_gphase = 0; }
        int b = batch[i];
        if (i == 0 || batch[i - 1] != b) g_gstart[b] = i;
        if (i == NN - 1 || batch[i + 1] != b) g_gend[b] = i + 1;
        return;
    }
    i -= NN;
    if (i < OUTSZ) out[i] = 0.0f;
}

// ---------------------------------------------------------------
// fused CSR builder: deg -> barrier -> dis+scan -> barrier -> fill
__global__ __launch_bounds__(256, 1) void k_csr(const int* __restrict__ ei) {
    const int b = blockIdx.x, t = threadIdx.x;
    const int gt = b * 256 + t;
    const int NT = CSRB * 256;

    for (int e = gt; e < EE; e += NT)
        atomicAdd(&g_degi[ei[e]], 1);
    gbar(1);

    if (b < NB) {
        __shared__ int sm[256];
        __shared__ int red[8];
        const int i = b * 256 + t;
        int d = 0;
        if (i < NN) {
            d = g_degi[i];
            g_dis[i] = (d > 0) ? rsqrtf((float)d) : 0.0f;
        }
        sm[t] = d;
        __syncthreads();
#pragma unroll
        for (int off = 1; off < 256; off <<= 1) {
            int u = (t >= off) ? sm[t - off] : 0;
            __syncthreads();
            sm[t] += u;
            __syncthreads();
        }
        const int total = sm[255];
        const int local_ex = sm[t] - d;
        if (t == 0) {
            __threadfence();
            atomicExch(&g_bsum[b], total);
        }
        int pred = 0;
        if (t < b) {
            volatile int* vb = g_bsum;
            int v;
            do { v = vb[t]; } while (v < 0);
            pred = v;
        }
        int v = pred;
#pragma unroll
        for (int off = 16; off; off >>= 1) v += __shfl_down_sync(0xffffffffu, v, off);
        if ((t & 31) == 0) red[t >> 5] = v;
        __syncthreads();
        if (t < 8) {
            int s = red[t];
#pragma unroll
            for (int off = 4; off; off >>= 1) s += __shfl_down_sync(0xffu, s, off);
            if (t == 0) red[0] = s;
        }
        __syncthreads();
        const int base = red[0];
        if (i < NN) {
            g_rowptr[i] = base + local_ex;
            g_cnt[i]    = base + local_ex;
        }
        if (b == NB - 1 && t == 255) g_rowptr[NN] = base + total;
    }
    gbar(2);

    for (int e = gt; e < EE; e += NT) {
        int r = ei[e];
        int c = ei[e + EE];
        int pos = atomicAdd(&g_cnt[r], 1);
        g_ccol[pos] = c;
        g_cw[pos]   = -(g_dis[r] * g_dis[c]);
    }
}

// ---------------------------------------------------------------
// SpMM (fp16 input, 4-way unrolled): p[v,:] = sum w * h16[col,:]; fp32 accum.
__global__ void k_spmm(int layer) {
    int w = (blockIdx.x * blockDim.x + threadIdx.x) >> 5;
    int lane = threadIdx.x & 31;
    if (w >= NN) return;
    const __half* hin = g_hb + (size_t)(layer & 1) * HSZ;

    float acc[8];
#pragma unroll
    for (int q = 0; q < 8; q++) acc[q] = 0.f;

    const int s = g_rowptr[w], e = g_rowptr[w + 1];
    int i = s;
    for (; i + 3 < e; i += 4) {
        int u0 = g_ccol[i], u1 = g_ccol[i + 1], u2 = g_ccol[i + 2], u3 = g_ccol[i + 3];
        float w0 = g_cw[i], w1 = g_cw[i + 1], w2 = g_cw[i + 2], w3 = g_cw[i + 3];
        uint4 r0 = __ldg(reinterpret_cast<const uint4*>(hin + (size_t)u0 * CC + lane * 8));
        uint4 r1 = __ldg(reinterpret_cast<const uint4*>(hin + (size_t)u1 * CC + lane * 8));
        uint4 r2 = __ldg(reinterpret_cast<const uint4*>(hin + (size_t)u2 * CC + lane * 8));
        uint4 r3 = __ldg(reinterpret_cast<const uint4*>(hin + (size_t)u3 * CC + lane * 8));
        const __half2* h0 = reinterpret_cast<const __half2*>(&r0);
        const __half2* h1 = reinterpret_cast<const __half2*>(&r1);
        const __half2* h2 = reinterpret_cast<const __half2*>(&r2);
        const __half2* h3 = reinterpret_cast<const __half2*>(&r3);
#pragma unroll
        for (int q = 0; q < 4; q++) {
            float2 f0 = __half22float2(h0[q]);
            float2 f1 = __half22float2(h1[q]);
            float2 f2 = __half22float2(h2[q]);
            float2 f3 = __half22float2(h3[q]);
            acc[2 * q]     += w0 * f0.x + w1 * f1.x + w2 * f2.x + w3 * f3.x;
            acc[2 * q + 1] += w0 * f0.y + w1 * f1.y + w2 * f2.y + w3 * f3.y;
        }
    }
    for (; i < e; i++) {
        int u = g_ccol[i];
        float wt = g_cw[i];
        uint4 raw = __ldg(reinterpret_cast<const uint4*>(hin + (size_t)u * CC + lane * 8));
        const __half2* hp = reinterpret_cast<const __half2*>(&raw);
#pragma unroll
        for (int q = 0; q < 4; q++) {
            float2 f = __half22float2(hp[q]);
            acc[2 * q]     += wt * f.x;
            acc[2 * q + 1] += wt * f.y;
        }
    }
    size_t o = (size_t)w * CC + lane * 8;
    __half2* pb = reinterpret_cast<__half2*>(g_pb + o);
#pragma unroll
    for (int q = 0; q < 4; q++)
        pb[q] = __halves2half2(__float2half_rn(acc[2 * q]), __float2half_rn(acc[2 * q + 1]));
}

// ---------------------------------------------------------------
// Tile loader (512 threads): A 128x64 fp16 + B 128x64 fp16, 144 B row pitch.
__device__ __forceinline__ void issue_tile(
    uint32_t sb, int stage, int kt, int m0, int n0,
    const __half* __restrict__ hb, const __half* __restrict__ wb, int tid)
{
    uint32_t base = sb + stage * STG_BYTES;
    int kbase = kt * 64;
    const __half* ab; int acol;
    if (kbase < CC) { ab = hb;   acol = kbase; }
    else            { ab = g_pb; acol = kbase - CC; }
#pragma unroll
    for (int rep = 0; rep < 2; rep++) {
        int idx = tid + rep * 512;       // 0..1023
        int r   = idx >> 3;              // 0..127
        int ch  = idx & 7;               // 0..7
        int gr = m0 + r;
        int sz = (gr < NN) ? 16 : 0;
        if (gr >= NN) gr = NN - 1;
        cpa16(base + r * APITCH + ch * 16,
              ab + (size_t)gr * CC + acol + ch * 8, sz);
    }
#pragma unroll
    for (int rep = 0; rep < 2; rep++) {
        int idx = tid + rep * 512;       // 0..1023
        int r   = idx >> 3;
        int ch  = idx & 7;
        cpa16(base + STG_A + r * APITCH + ch * 16,
              wb + (size_t)(n0 + r) * KDIM + kbase + ch * 8, 16);
    }
}

// ---------------------------------------------------------------
// fp16 GEMM, BM=128 BN=128 BK=64, 512 thr, 16 warps 4m x 4n (warp tile 32x32),
// 2 CTAs/SM, double-buffered, 8 barriers total. cp.async.cg, batched LDSM.
// Fused BN/ReLU + next-layer fp16 store + graph-mean-pool accumulation.
__global__ __launch_bounds__(512, 2) void k_gemm(
    const float* __restrict__ gamma,
    const float* __restrict__ beta,
    float* __restrict__ out,
    int layer)
{
    extern __shared__ char smc[];
    uint32_t sb = smem_u32(smc);
    const int tid = threadIdx.x;
    const int wid = tid >> 5, lane = tid & 31;
    const int wm = wid >> 2, wn = wid & 3;       // 4 x 4 warps
    const int gid = lane >> 2, tig = lane & 3;
    const int lrow = lane & 7, grp = lane >> 3;
    const int m0 = blockIdx.x * 128;
    const int n0 = blockIdx.y * 128;

    const __half* hb = g_hb + (size_t)(layer & 1) * HSZ;
    const __half* wb = g_wb + (size_t)layer * CC * KDIM;

    float acc[2][4][4];
#pragma unroll
    for (int mi = 0; mi < 2; mi++)
#pragma unroll
        for (int ni = 0; ni < 4; ni++)
#pragma unroll
            for (int r = 0; r < 4; r++) acc[mi][ni][r] = 0.f;

    const uint32_t a_row = (uint32_t)(wm * 32 + ((grp & 1) << 3) + lrow) * APITCH;
    const uint32_t a_kof = (uint32_t)((grp >> 1) << 3) * 2;
    const uint32_t b_row = (uint32_t)(wn * 32 + ((grp >> 1) << 3) + lrow) * APITCH;
    const uint32_t b_kof = (uint32_t)((grp & 1) << 3) * 2;

    issue_tile(sb, 0, 0, m0, n0, hb, wb, tid);
    asm volatile("cp.async.commit_group;");

    for (int kt = 0; kt < 8; kt++) {
        asm volatile("cp.async.wait_group 0;");
        __syncthreads();
        // prefetch next tile into the buffer compute(kt-1) released
        if (kt + 1 < 8) {
            issue_tile(sb, (kt + 1) & 1, kt + 1, m0, n0, hb, wb, tid);
            asm volatile("cp.async.commit_group;");
        }

        const uint32_t stg = sb + (kt & 1) * STG_BYTES;
#pragma unroll
        for (int ks = 0; ks < 4; ks++) {
            const uint32_t kk2 = (uint32_t)ks * 32;   // 16 halves * 2 B
            uint32_t bb[4][2];
            uint32_t aa[2][4];
#pragma unroll
            for (int np = 0; np < 2; np++) {
                uint32_t baddr = stg + STG_A + np * 16 * APITCH + b_row + kk2 + b_kof;
                ldmx4(bb[2 * np][0], bb[2 * np][1], bb[2 * np + 1][0], bb[2 * np + 1][1], baddr);
            }
#pragma unroll
            for (int mi = 0; mi < 2; mi++) {
                uint32_t aaddr = stg + mi * 16 * APITCH + a_row + kk2 + a_kof;
                ldmx4(aa[mi][0], aa[mi][1], aa[mi][2], aa[mi][3], aaddr);
            }
#pragma unroll
            for (int mi = 0; mi < 2; mi++)
#pragma unroll
                for (int ni = 0; ni < 4; ni++)
                    mma_f16(acc[mi][ni][0], acc[mi][ni][1], acc[mi][ni][2], acc[mi][ni][3],
                            aa[mi][0], aa[mi][1], aa[mi][2], aa[mi][3],
                            bb[ni][0], bb[ni][1]);
        }
    }

    // epilogue: BN/ReLU -> next-layer fp16 (layers 0,1) + fused pool sums.
    const float inv = rsqrtf(1.0f + 1e-5f);
    __half* ob = g_hb + (size_t)((layer + 1) & 1) * HSZ;
    const bool wr_next = (layer < 2);
    const int gbase = m0 / 400;
#pragma unroll
    for (int ni = 0; ni < 4; ni++) {
        int c = n0 + wn * 32 + ni * 8 + 2 * tig;
        float s0 = __ldg(&gamma[layer * CC + c])     * inv;
        float s1 = __ldg(&gamma[layer * CC + c + 1]) * inv;
        float b0 = __ldg(&beta[layer * CC + c]);
        float b1 = __ldg(&beta[layer * CC + c + 1]);
        float ps[2][2] = {{0.f, 0.f}, {0.f, 0.f}};
#pragma unroll
        for (int mi = 0; mi < 2; mi++) {
            int r0 = m0 + wm * 32 + mi * 16 + gid;
            int r1 = r0 + 8;
            float v0 = acc[mi][ni][0], v1 = acc[mi][ni][1];
            float v2 = acc[mi][ni][2], v3 = acc[mi][ni][3];
            float o0, o1, o2, o3;
            if (layer == 0) {
                o0 = fmaxf(v0 * s0 + b0, 0.f); o1 = fmaxf(v1 * s1 + b1, 0.f);
                o2 = fmaxf(v2 * s0 + b0, 0.f); o3 = fmaxf(v3 * s1 + b1, 0.f);
            } else {
                o0 = fmaxf(v0, 0.f) * s0 + b0; o1 = fmaxf(v1, 0.f) * s1 + b1;
                o2 = fmaxf(v2, 0.f) * s0 + b0; o3 = fmaxf(v3, 0.f) * s1 + b1;
            }
            if (r0 < NN) {
                int sg = r0 / 400 - gbase;
                ps[sg][0] += o0; ps[sg][1] += o1;
                if (wr_next)
                    *reinterpret_cast<__half2*>(&ob[(size_t)r0 * CC + c]) =
                        __halves2half2(__float2half_rn(o0), __float2half_rn(o1));
            }
            if (r1 < NN) {
                int sg = r1 / 400 - gbase;
                ps[sg][0] += o2; ps[sg][1] += o3;
                if (wr_next)
                    *reinterpret_cast<__half2*>(&ob[(size_t)r1 * CC + c]) =
                        __halves2half2(__float2half_rn(o2), __float2half_rn(o3));
            }
        }
#pragma unroll
        for (int sg = 0; sg < 2; sg++) {
#pragma unroll
            for (int cp = 0; cp < 2; cp++) {
                float v = ps[sg][cp];
                v += __shfl_down_sync(0xffffffffu, v, 16);
                v += __shfl_down_sync(0xffffffffu, v, 8);
                v += __shfl_down_sync(0xffffffffu, v, 4);
                if (lane < 4) {
                    int g = gbase + sg;
                    if (g < GG)
                        atomicAdd(&out[(size_t)g * JKW + layer * CC + c + cp], v);
                }
            }
        }
    }
}

// ---------------------------------------------------------------
// classifier: divide pool sums -> write mean -> Linear/ReLU/BN/Linear
__global__ void k_cls(const float* __restrict__ W1, const float* __restrict__ b1,
                      const float* __restrict__ cg, const float* __restrict__ cbe,
                      const float* __restrict__ W2, const float* __restrict__ b2,
                      float* __restrict__ out)
{
    __shared__ float zr[JKW];
    __shared__ float zz[256];
    int g = blockIdx.x, t = threadIdx.x;
    float rc = 1.0f / (float)(g_gend[g] - g_gstart[g]);
    for (int j = t; j < JKW; j += 256) {
        float v = out[(size_t)g * JKW + j] * rc;
        zr[j] = v;
        out[(size_t)g * JKW + j] = v;
    }
    __syncthreads();

    float acc = b1[t];
    const float* w = W1 + (size_t)t * JKW;
    for (int j = 0; j < JKW; j++) acc += zr[j] * w[j];
    const float inv = rsqrtf(1.0f + 1e-5f);
    zz[t] = fmaxf(acc, 0.f) * cg[t] * inv + cbe[t];
    __syncthreads();

    if (t < 64) {
        int k = t >> 5;
        int lane = t & 31;
        float s = 0.f;
        for (int o = lane; o < 256; o += 32) s += zz[o] * W2[k * 256 + o];
#pragma unroll
        for (int off = 16; off; off >>= 1) s += __shfl_down_sync(0xffffffffu, s, off);
        if (lane == 0) out[GG * JKW + g * 2 + k] = s + b2[k];
    }
}

// ---------------------------------------------------------------
extern "C" void kernel_launch(void* const* d_in, const int* in_sizes, int n_in,
                              void* d_out, int out_size)
{
    const float* x    = (const float*)d_in[0];
    const int*   ei   = (const int*)  d_in[1];
    const int*   batch= (const int*)  d_in[2];
    const float* cw   = (const float*)d_in[3];
    const float* bg   = (const float*)d_in[4];
    const float* bb   = (const float*)d_in[5];
    const float* w1   = (const float*)d_in[6];
    const float* b1   = (const float*)d_in[7];
    const float* cg   = (const float*)d_in[8];
    const float* cbe  = (const float*)d_in[9];
    const float* w2   = (const float*)d_in[10];
    const float* b2   = (const float*)d_in[11];
    float* out = (float*)d_out;

    cudaFuncSetAttribute(k_gemm, cudaFuncAttributeMaxDynamicSharedMemorySize, SMEM_TOT);

    int prep_total = PREP_X + PREP_W + NN + OUTSZ;
    k_prep<<<(prep_total + 255) / 256, 256>>>(x, cw, batch, out);
    k_csr<<<CSRB, 256>>>(ei);

    for (int l = 0; l < 3; l++) {
        k_spmm<<<(NN + 7) / 8, 256>>>(l);
        dim3 grid((NN + 127) / 128, 2);
        k_gemm<<<grid, 512, SMEM_TOT>>>(bg, bb, out, l);
    }

    k_cls<<<GG, 256>>>(w1, b1, cg, cbe, w2, b2, out);
}